// round 3
// baseline (speedup 1.0000x reference)
#include <cuda_runtime.h>
#include <cuda_bf16.h>
#include <math.h>

#define NN 50000
#define EE 800000
#define NODE_IN 128
#define HID 256
#define OUT_D 256
#define EDGE_DIM 16
#define HEADS 4
#define CH 64

// ---------------- scratch (static device globals; no allocation allowed) ----
__device__ float g_xcat[(size_t)NN * 512];     // [N, 2*HID] concat input to GAT1
__device__ float g_xh[(size_t)NN * 256];       // xh for current layer
__device__ float g_h[(size_t)NN * 256];        // layer output (h1 then h2)
__device__ float g_nefsum[(size_t)NN * EDGE_DIM];
__device__ int   g_cnt[NN];
__device__ int   g_off[NN + 1];
__device__ int   g_cur[NN];
__device__ int   g_csr[EE];
__device__ float g_asrc[NN * HEADS];
__device__ float g_adst[NN * HEADS];
__device__ int   g_src[EE];
__device__ int   g_dst[EE];
__device__ int   g_is64;

// ---------------- small helpers -------------------------------------------
__device__ __forceinline__ float lrelu(float x) { return x > 0.f ? x : 0.2f * x; }
__device__ __forceinline__ float elu(float x)   { return x > 0.f ? x : expf(x) - 1.f; }
__device__ __forceinline__ float wredmax(float v) {
    #pragma unroll
    for (int o = 16; o; o >>= 1) v = fmaxf(v, __shfl_xor_sync(0xffffffffu, v, o));
    return v;
}
__device__ __forceinline__ float wredsum(float v) {
    #pragma unroll
    for (int o = 16; o; o >>= 1) v += __shfl_xor_sync(0xffffffffu, v, o);
    return v;
}

// ---------------- kernels --------------------------------------------------

// Detect whether edge_index buffer is int64 (odd 32-bit words all zero) or int32.
__global__ void detect_kernel(const int* __restrict__ ei_raw) {
    if (threadIdx.x == 0) {
        int any = 0;
        #pragma unroll 1
        for (int i = 1; i < 256; i += 2) any |= ei_raw[i];
        g_is64 = (any == 0) ? 1 : 0;
    }
}

// Materialize int32 src/dst under either storage layout. Clamp defensively.
__global__ void convert_edges(const int* __restrict__ ei_raw) {
    int e = blockIdx.x * blockDim.x + threadIdx.x;
    if (e >= EE) return;
    int s, d;
    if (g_is64) {
        s = ei_raw[2 * (size_t)e];
        d = ei_raw[2 * ((size_t)EE + e)];
    } else {
        s = ei_raw[e];
        d = ei_raw[EE + e];
    }
    s = min(max(s, 0), NN - 1);
    d = min(max(d, 0), NN - 1);
    g_src[e] = s;
    g_dst[e] = d;
}

// zero counters + nef sums (must re-run every replay)
__global__ void zero_kernel() {
    int i = blockIdx.x * blockDim.x + threadIdx.x;
    int total = NN * EDGE_DIM;  // 800000
    for (int k = i; k < total; k += gridDim.x * blockDim.x) g_nefsum[k] = 0.f;
    for (int k = i; k < NN; k += gridDim.x * blockDim.x) g_cnt[k] = 0;
}

// pass over edges: degree count + edge_attr scatter-sum by dst
__global__ void edge_count_nef(const float* __restrict__ eattr) {
    int e = blockIdx.x * blockDim.x + threadIdx.x;
    if (e >= EE) return;
    int dst = g_dst[e];
    atomicAdd(&g_cnt[dst], 1);
    const float* ea = eattr + (size_t)e * EDGE_DIM;
    float* ns = g_nefsum + (size_t)dst * EDGE_DIM;
    #pragma unroll
    for (int k = 0; k < EDGE_DIM; k++) atomicAdd(&ns[k], ea[k]);
}

// single-block exclusive scan of g_cnt -> g_off, init g_cur
__global__ void prefix_kernel() {
    __shared__ int sh[1024];
    const int CHK = (NN + 1023) / 1024;  // 49
    int t = threadIdx.x;
    int start = t * CHK;
    int stop = min(start + CHK, NN);
    int s = 0;
    for (int i = start; i < stop; i++) s += g_cnt[i];
    sh[t] = s;
    __syncthreads();
    #pragma unroll
    for (int off = 1; off < 1024; off <<= 1) {
        int v = (t >= off) ? sh[t - off] : 0;
        __syncthreads();
        sh[t] += v;
        __syncthreads();
    }
    int run = sh[t] - s;  // exclusive prefix
    for (int i = start; i < stop; i++) {
        g_off[i] = run;
        g_cur[i] = run;
        run += g_cnt[i];
    }
    if (t == 1023) g_off[NN] = sh[1023];
}

// fill CSR src lists
__global__ void edge_fill_csr() {
    int e = blockIdx.x * blockDim.x + threadIdx.x;
    if (e >= EE) return;
    int pos = atomicAdd(&g_cur[g_dst[e]], 1);
    g_csr[pos] = g_src[e];
}

// generic tiled fp32 GEMM: C[M,256] = A[M,K] @ W[K,256] (+ bias)
// BM=BN=64, BK=16, 256 threads, 4x4 per thread
__global__ void gemm_bias(const float* __restrict__ A, int lda,
                          const float* __restrict__ W,
                          const float* __restrict__ bias,
                          float* __restrict__ C, int ldc,
                          int M, int K) {
    __shared__ float As[16][64];
    __shared__ float Bs[16][64];
    int bm = blockIdx.y * 64;
    int bn = blockIdx.x * 64;
    int tid = threadIdx.x;
    int tx = tid & 15, ty = tid >> 4;

    float acc[4][4];
    #pragma unroll
    for (int i = 0; i < 4; i++)
        #pragma unroll
        for (int j = 0; j < 4; j++) acc[i][j] = 0.f;

    int arow = tid >> 2;        // 0..63
    int acol = (tid & 3) * 4;   // 0..12
    int wrow = tid >> 4;        // 0..15
    int wcol = (tid & 15) * 4;  // 0..60

    for (int k0 = 0; k0 < K; k0 += 16) {
        int gr = bm + arow;
        float4 av = make_float4(0.f, 0.f, 0.f, 0.f);
        if (gr < M) av = *reinterpret_cast<const float4*>(A + (size_t)gr * lda + k0 + acol);
        As[acol + 0][arow] = av.x;
        As[acol + 1][arow] = av.y;
        As[acol + 2][arow] = av.z;
        As[acol + 3][arow] = av.w;
        float4 wv = *reinterpret_cast<const float4*>(W + (size_t)(k0 + wrow) * 256 + bn + wcol);
        *reinterpret_cast<float4*>(&Bs[wrow][wcol]) = wv;
        __syncthreads();
        #pragma unroll
        for (int kk = 0; kk < 16; kk++) {
            float4 a4 = *reinterpret_cast<const float4*>(&As[kk][ty * 4]);
            float4 b4 = *reinterpret_cast<const float4*>(&Bs[kk][tx * 4]);
            float a[4] = {a4.x, a4.y, a4.z, a4.w};
            float b[4] = {b4.x, b4.y, b4.z, b4.w};
            #pragma unroll
            for (int i = 0; i < 4; i++)
                #pragma unroll
                for (int j = 0; j < 4; j++) acc[i][j] += a[i] * b[j];
        }
        __syncthreads();
    }
    #pragma unroll
    for (int i = 0; i < 4; i++) {
        int r = bm + ty * 4 + i;
        if (r >= M) continue;
        #pragma unroll
        for (int j = 0; j < 4; j++) {
            int c = bn + tx * 4 + j;
            float bv = bias ? bias[c] : 0.f;
            C[(size_t)r * ldc + c] = acc[i][j] + bv;
        }
    }
}

// fused: nef = (nefsum / max(cnt,1)) @ Wep + bep -> g_xcat[:, 256:512]
__global__ void edgeproj_kernel(const float* __restrict__ Wep,
                                const float* __restrict__ bep) {
    __shared__ float sW[EDGE_DIM * 256];
    __shared__ float snef[EDGE_DIM];
    int tid = threadIdx.x;  // 256
    for (int i = tid; i < EDGE_DIM * 256; i += 256) sW[i] = Wep[i];
    float bv = bep[tid];
    int nbase = blockIdx.x * 16;
    for (int u = 0; u < 16; u++) {
        int n = nbase + u;
        __syncthreads();
        if (n < NN && tid < EDGE_DIM) {
            float c = (float)g_cnt[n];
            snef[tid] = g_nefsum[(size_t)n * EDGE_DIM + tid] / fmaxf(c, 1.0f);
        }
        __syncthreads();
        if (n < NN) {
            float acc = bv;
            #pragma unroll
            for (int k = 0; k < EDGE_DIM; k++) acc += snef[k] * sW[k * 256 + tid];
            g_xcat[(size_t)n * 512 + 256 + tid] = acc;
        }
    }
}

// per-node attention dot products: a_src[n,h] = xh[n,h,:]·as[h,:]
__global__ void attn_dots(const float* __restrict__ as_p,
                          const float* __restrict__ ad_p) {
    int n = blockIdx.x;
    int h = threadIdx.x >> 5;
    int l = threadIdx.x & 31;
    const float* row = g_xh + (size_t)n * 256 + h * CH;
    float x0 = row[l], x1 = row[l + 32];
    float s = x0 * as_p[h * CH + l] + x1 * as_p[h * CH + l + 32];
    float d = x0 * ad_p[h * CH + l] + x1 * ad_p[h * CH + l + 32];
    s = wredsum(s);
    d = wredsum(d);
    if (l == 0) {
        g_asrc[n * HEADS + h] = s;
        g_adst[n * HEADS + h] = d;
    }
}

// gather-based GAT aggregation with implicit self-loop, fused bias + ELU
__global__ void gat_aggregate(const float* __restrict__ bias,
                              float* __restrict__ out) {
    int n = blockIdx.x;
    int h = threadIdx.x >> 5;
    int l = threadIdx.x & 31;
    int off = g_off[n];
    int deg = g_off[n + 1] - off;
    float adst = g_adst[n * HEADS + h];
    float slf = lrelu(g_asrc[n * HEADS + h] + adst);

    // pass 1: max
    float m = slf;
    for (int e = l; e < deg; e += 32) {
        int s = g_csr[off + e];
        m = fmaxf(m, lrelu(g_asrc[s * HEADS + h] + adst));
    }
    m = wredmax(m);

    // pass 2: denom
    float ds = 0.f;
    for (int e = l; e < deg; e += 32) {
        int s = g_csr[off + e];
        ds += expf(lrelu(g_asrc[s * HEADS + h] + adst) - m);
    }
    ds = wredsum(ds) + expf(slf - m);
    float inv = 1.0f / ds;

    // pass 3: weighted gather (all 32 lanes cooperate per edge; lane = channel)
    const float* xr = g_xh + (size_t)n * 256 + h * CH;
    float wslf = expf(slf - m) * inv;
    float a0 = wslf * xr[l];
    float a1 = wslf * xr[l + 32];
    int e = 0;
    for (; e + 1 < deg; e += 2) {
        int s0 = g_csr[off + e];
        int s1 = g_csr[off + e + 1];
        float w0 = expf(lrelu(g_asrc[s0 * HEADS + h] + adst) - m) * inv;
        float w1 = expf(lrelu(g_asrc[s1 * HEADS + h] + adst) - m) * inv;
        const float* r0 = g_xh + (size_t)s0 * 256 + h * CH;
        const float* r1 = g_xh + (size_t)s1 * 256 + h * CH;
        a0 += w0 * r0[l] + w1 * r1[l];
        a1 += w0 * r0[l + 32] + w1 * r1[l + 32];
    }
    if (e < deg) {
        int s0 = g_csr[off + e];
        float w0 = expf(lrelu(g_asrc[s0 * HEADS + h] + adst) - m) * inv;
        const float* r0 = g_xh + (size_t)s0 * 256 + h * CH;
        a0 += w0 * r0[l];
        a1 += w0 * r0[l + 32];
    }
    float b0 = bias[h * CH + l];
    float b1 = bias[h * CH + l + 32];
    out[(size_t)n * 256 + h * CH + l]      = elu(a0 + b0);
    out[(size_t)n * 256 + h * CH + l + 32] = elu(a1 + b1);
}

// ---------------- launch ----------------------------------------------------
extern "C" void kernel_launch(void* const* d_in, const int* in_sizes, int n_in,
                              void* d_out, int out_size) {
    const float* node_feats = (const float*)d_in[0];
    const float* edge_attr  = (const float*)d_in[1];
    const float* Wnp = (const float*)d_in[2];
    const float* bnp = (const float*)d_in[3];
    const float* Wep = (const float*)d_in[4];
    const float* bep = (const float*)d_in[5];
    const float* Wg1 = (const float*)d_in[6];
    const float* as1 = (const float*)d_in[7];
    const float* ad1 = (const float*)d_in[8];
    const float* bg1 = (const float*)d_in[9];
    const float* Wg2 = (const float*)d_in[10];
    const float* as2 = (const float*)d_in[11];
    const float* ad2 = (const float*)d_in[12];
    const float* bg2 = (const float*)d_in[13];
    const float* Wo  = (const float*)d_in[14];
    const float* bo  = (const float*)d_in[15];
    const int* ei_raw = (const int*)d_in[16];
    float* out = (float*)d_out;

    float* xcat; cudaGetSymbolAddress((void**)&xcat, g_xcat);
    float* xh;   cudaGetSymbolAddress((void**)&xh,   g_xh);
    float* hbuf; cudaGetSymbolAddress((void**)&hbuf, g_h);

    const int EB = (EE + 255) / 256;

    // edge index normalization (handles int32 or int64 storage)
    detect_kernel<<<1, 32>>>(ei_raw);
    convert_edges<<<EB, 256>>>(ei_raw);

    // graph build + edge aggregation
    zero_kernel<<<592, 256>>>();
    edge_count_nef<<<EB, 256>>>(edge_attr);
    prefix_kernel<<<1, 1024>>>();
    edge_fill_csr<<<EB, 256>>>();

    dim3 ggrid(4, (NN + 63) / 64);  // 256 cols / 64, M tiles

    // node_proj -> xcat[:, :256]
    gemm_bias<<<ggrid, 256>>>(node_feats, NODE_IN, Wnp, bnp, xcat, 512, NN, NODE_IN);
    // edge_proj -> xcat[:, 256:512]
    edgeproj_kernel<<<(NN + 15) / 16, 256>>>(Wep, bep);

    // ---- GAT layer 1 ----
    gemm_bias<<<ggrid, 256>>>(xcat, 512, Wg1, nullptr, xh, 256, NN, 512);
    attn_dots<<<NN, 128>>>(as1, ad1);
    gat_aggregate<<<NN, 128>>>(bg1, hbuf);

    // ---- GAT layer 2 ----
    gemm_bias<<<ggrid, 256>>>(hbuf, 256, Wg2, nullptr, xh, 256, NN, 256);
    attn_dots<<<NN, 128>>>(as2, ad2);
    gat_aggregate<<<NN, 128>>>(bg2, hbuf);

    // ---- out_proj -> d_out ----
    gemm_bias<<<ggrid, 256>>>(hbuf, 256, Wo, bo, out, 256, NN, 256);
}